// round 3
// baseline (speedup 1.0000x reference)
#include <cuda_runtime.h>

#define INVS2 0.70710678118654752440f

// ---------------- scratch (__device__ globals; no dynamic alloc) ----------------
__device__ __align__(128) float g_E1[129 * 128];        // emb @ W1
__device__ __align__(128) float g_wk[4 * 21 * 24];      // w[c,k] = 0.5*Cl[c,k,:], k=1..4, padded to 24
__device__ __align__(128) float g_w0[21 * 24];          // w[c,0], padded to 24
__device__ __align__(128) float g_const[21];            // sum_t Cl[c,t,:]·b2
__device__ __align__(128) float g_C0[129 * 32];         // const[c] + p0(n0)·w[c,0], row pitch 32
__device__ __align__(128) float g_T[4 * 129 * 129 * 32];// T[k][n0][nk][c], row pitch 32 (128B)
__device__ int g_is64;

// ---------------- dtype detector (int64 vs silently-downcast int32) -------------
__global__ void kDetect(const int* __restrict__ inst) {
    __shared__ int any_nz;
    if (threadIdx.x == 0) any_nz = 0;
    __syncthreads();
    int nz = 0;
    // If data is little-endian int64 with values < 129, every odd int32 word is 0.
    // If data is int32 node values (0..128), odd words are node values, ~99% nonzero.
    for (int i = threadIdx.x; i < 4096; i += blockDim.x)
        if (inst[2 * i + 1] != 0) nz = 1;
    if (nz) atomicOr(&any_nz, 1);
    __syncthreads();
    if (threadIdx.x == 0) g_is64 = any_nz ? 0 : 1;
}

__device__ __forceinline__ int load_idx(const void* p, long long i, int is64) {
    return is64 ? (int)((const long long*)p)[i] : ((const int*)p)[i];
}

// ---------------- A1: E1 = emb @ W1  ([129,21]@[21,128]) ------------------------
__global__ void kA1(const float* __restrict__ emb, const float* __restrict__ W1) {
    int o = blockIdx.x * blockDim.x + threadIdx.x;
    if (o >= 129 * 128) return;
    int i = o >> 7, j = o & 127;
    float acc = 0.f;
    #pragma unroll
    for (int d = 0; d < 21; d++) acc = fmaf(emb[i * 21 + d], W1[d * 128 + j], acc);
    g_E1[o] = acc;
}

// ---------------- A2: class branch -> w tables + const (one block per class) ----
__global__ __launch_bounds__(128) void kA2(const void* __restrict__ cn,
                                           const float* __restrict__ emb,
                                           const float* __restrict__ W1,
                                           const float* __restrict__ b1,
                                           const float* __restrict__ W2,
                                           const float* __restrict__ b2) {
    __shared__ float sx[105], sh[640], sr[640], sp[105], sCl[105];
    int c = blockIdx.x, t = threadIdx.x;
    int is64 = g_is64;
    if (t < 105) {
        int s = t / 21, d = t - s * 21;
        int node = load_idx(cn, c * 5 + s, is64);
        sx[t] = emb[node * 21 + d];
    }
    __syncthreads();
    // xW1 [5,128]
    for (int o = t; o < 640; o += 128) {
        int s = o >> 7, j = o & 127;
        float a = 0.f;
        #pragma unroll
        for (int d = 0; d < 21; d++) a = fmaf(sx[s * 21 + d], W1[d * 128 + j], a);
        sh[o] = a;
    }
    __syncthreads();
    // h = M-prop + b1, relu
    for (int o = t; o < 640; o += 128) {
        int s = o >> 7, j = o & 127;
        float v = (s == 0) ? sh[j] : fmaf(0.5f, sh[o], INVS2 * sh[j]);
        sr[o] = fmaxf(v + b1[j], 0.f);
    }
    __syncthreads();
    // rW2 [5,21]
    if (t < 105) {
        int s = t / 21, d = t - s * 21;
        float a = 0.f;
        for (int j = 0; j < 128; j++) a = fmaf(sr[s * 128 + j], W2[j * 21 + d], a);
        sp[t] = a;
    }
    __syncthreads();
    // Cl = M-prop + b2 [5,21]
    if (t < 105) {
        int s = t / 21, d = t - s * 21;
        float v = (s == 0) ? sp[d] : fmaf(0.5f, sp[t], INVS2 * sp[d]);
        sCl[t] = v + b2[d];
    }
    __syncthreads();
    // w[c,k,:] = 0.5*Cl[c,k,:] for k=1..4 (padded to 24)
    if (t < 96) {
        int k = t / 24, d = t - k * 24;
        g_wk[(k * 21 + c) * 24 + d] = (d < 21) ? 0.5f * sCl[(k + 1) * 21 + d] : 0.f;
    }
    // w[c,0,:] = Cl[0] + inv_sqrt2 * sum_k Cl[k]
    if (t < 24)
        g_w0[c * 24 + t] = (t < 21)
            ? sCl[t] + INVS2 * (sCl[21 + t] + sCl[42 + t] + sCl[63 + t] + sCl[84 + t])
            : 0.f;
    if (t == 0) {
        float a = 0.f;
        for (int s = 0; s < 5; s++)
            for (int d = 0; d < 21; d++) a = fmaf(sCl[s * 21 + d], b2[d], a);
        g_const[c] = a;
    }
}

// ---------------- A3: C0[n0][c] = const[c] + p0(n0)·w[c,0]  (block per n0) ------
__global__ __launch_bounds__(128) void kA3(const float* __restrict__ b1,
                                           const float* __restrict__ W2) {
    __shared__ float sr[128], sp[24];
    int n0 = blockIdx.x, t = threadIdx.x;
    sr[t] = fmaxf(g_E1[n0 * 128 + t] + b1[t], 0.f);
    __syncthreads();
    if (t < 24) {
        float a = 0.f;
        if (t < 21)
            for (int j = 0; j < 128; j++) a = fmaf(sr[j], W2[j * 21 + t], a);
        sp[t] = a;
    }
    __syncthreads();
    if (t < 32) {
        float v = 0.f;
        if (t < 21) {
            v = g_const[t];
            #pragma unroll
            for (int d = 0; d < 21; d++) v = fmaf(sp[d], g_w0[t * 24 + d], v);
        }
        g_C0[n0 * 32 + t] = v;
    }
}

// ---------------- B: build T[k][n0][nk][c] tables --------------------------------
// thread = one (n0,nk) pair:  p = relu(0.5*E1[nk] + inv_sqrt2*E1[n0] + b1) @ W2,
// then T[k][..][c] = p · w[c,k+1].
#define SE1_PAD 16644  // 129*129 = 16641, rounded up so next region is 16B aligned
__global__ __launch_bounds__(128) void kB(const float* __restrict__ b1,
                                          const float* __restrict__ W2) {
    extern __shared__ float sm[];
    float* sE1 = sm;                   // [129][129] pitch 129 (conflict-free)
    float* sW2 = sm + SE1_PAD;         // [128][24]
    float* sw  = sW2 + 128 * 24;       // [4][21][24]
    float* sb1 = sw + 4 * 21 * 24;     // [128]
    int t = threadIdx.x;
    for (int i = t; i < 129 * 128; i += 128)
        sE1[(i >> 7) * 129 + (i & 127)] = g_E1[i];
    for (int i = t; i < 128 * 24; i += 128) {
        int j = i / 24, d = i - j * 24;
        sW2[i] = (d < 21) ? W2[j * 21 + d] : 0.f;
    }
    for (int i = t; i < 4 * 21 * 24; i += 128) sw[i] = g_wk[i];
    sb1[t] = b1[t];
    __syncthreads();

    int flat = blockIdx.x * 128 + t;
    if (flat >= 129 * 129) return;
    int n0 = flat / 129;
    int nk = flat - n0 * 129;

    float p[21];
    #pragma unroll
    for (int d = 0; d < 21; d++) p[d] = 0.f;

    const float* e0 = &sE1[n0 * 129];
    const float* ek = &sE1[nk * 129];
    #pragma unroll 4
    for (int j = 0; j < 128; j++) {
        float rv = fmaxf(fmaf(0.5f, ek[j], fmaf(INVS2, e0[j], sb1[j])), 0.f);
        float q[24];
        const float4* w4 = (const float4*)&sW2[j * 24];
        *(float4*)&q[0]  = w4[0];
        *(float4*)&q[4]  = w4[1];
        *(float4*)&q[8]  = w4[2];
        *(float4*)&q[12] = w4[3];
        *(float4*)&q[16] = w4[4];
        *(float4*)&q[20] = w4[5];
        #pragma unroll
        for (int d = 0; d < 21; d++) p[d] = fmaf(rv, q[d], p[d]);
    }

    #pragma unroll
    for (int k = 0; k < 4; k++) {
        float* dst = &g_T[(((k * 129) + n0) * 129 + nk) * 32];
        #pragma unroll 3
        for (int c = 0; c < 21; c++) {
            float q[24];
            const float4* w4 = (const float4*)&sw[(k * 21 + c) * 24];
            *(float4*)&q[0]  = w4[0];
            *(float4*)&q[4]  = w4[1];
            *(float4*)&q[8]  = w4[2];
            *(float4*)&q[12] = w4[3];
            *(float4*)&q[16] = w4[4];
            *(float4*)&q[20] = w4[5];
            float a0 = 0.f, a1 = 0.f, a2 = 0.f, a3 = 0.f;
            #pragma unroll
            for (int d = 0; d < 20; d += 4) {
                a0 = fmaf(p[d + 0], q[d + 0], a0);
                a1 = fmaf(p[d + 1], q[d + 1], a1);
                a2 = fmaf(p[d + 2], q[d + 2], a2);
                a3 = fmaf(p[d + 3], q[d + 3], a3);
            }
            a0 = fmaf(p[20], q[20], a0);
            dst[c] = (a0 + a1) + (a2 + a3);
        }
        dst[21] = 0.f; dst[22] = 0.f; dst[23] = 0.f;
    }
}

// ---------------- C: main per-pixel kernel (8 threads/pixel) ---------------------
// lane layout: sub = lane>>3 selects 1 of 4 pixels per warp, pp = lane&7 selects
// a float4 piece (pieces 0..5 cover the 24-float padded row; rows are 128B aligned
// so each gather is 1 L1 wavefront per pixel-row).
__global__ __launch_bounds__(256) void kC(const void* __restrict__ inst,
                                          float* __restrict__ out) {
    __shared__ float so[32 * 21];
    int t = threadIdx.x;
    int lane = t & 31, warp = t >> 5;
    int sub = lane >> 3, pp = lane & 7;
    int warpPix = blockIdx.x * 32 + warp * 4;
    long long base5 = (long long)warpPix * 5;
    int is64 = g_is64;
    int v = 0;
    if (lane < 20) v = load_idx(inst, base5 + lane, is64);
    int n0 = __shfl_sync(0xffffffffu, v, sub * 5);
    bool act = pp < 6;
    float4 acc = make_float4(0.f, 0.f, 0.f, 0.f);
    if (act) acc = *(const float4*)&g_C0[n0 * 32 + pp * 4];
    #pragma unroll
    for (int k = 0; k < 4; k++) {
        int nk = __shfl_sync(0xffffffffu, v, sub * 5 + k + 1);
        if (act) {
            float4 tv = *(const float4*)&g_T[(((k * 129) + n0) * 129 + nk) * 32 + pp * 4];
            acc.x += tv.x; acc.y += tv.y; acc.z += tv.z; acc.w += tv.w;
        }
    }
    int pib = warp * 4 + sub;
    if (act) {
        float vals[4] = {acc.x, acc.y, acc.z, acc.w};
        #pragma unroll
        for (int i = 0; i < 4; i++) {
            int c = pp * 4 + i;
            if (c < 21) so[pib * 21 + c] = vals[i];
        }
    }
    __syncthreads();
    // coalesced float4 copy out: block region is 32*21*4 = 2688B, 16B aligned
    const float4* s4 = (const float4*)so;
    float4* o4 = (float4*)(out + (long long)blockIdx.x * (32 * 21));
    if (t < 168) o4[t] = s4[t];
}

// ---------------- launch ---------------------------------------------------------
extern "C" void kernel_launch(void* const* d_in, const int* in_sizes, int n_in,
                              void* d_out, int out_size) {
    const void*  inst = d_in[0];                 // [4,256,256,5] int64 or int32
    const void*  cn   = d_in[1];                 // [21,5]
    const float* emb  = (const float*)d_in[2];   // [129,21]
    const float* W1   = (const float*)d_in[3];   // [21,128]
    const float* b1   = (const float*)d_in[4];   // [128]
    const float* W2   = (const float*)d_in[5];   // [128,21]
    const float* b2   = (const float*)d_in[6];   // [21]
    float* out = (float*)d_out;

    const size_t smB = (size_t)(SE1_PAD + 128 * 24 + 4 * 21 * 24 + 128) * sizeof(float);
    cudaFuncSetAttribute(kB, cudaFuncAttributeMaxDynamicSharedMemorySize, (int)smB);

    kDetect<<<1, 256>>>((const int*)inst);
    kA1<<<(129 * 128 + 255) / 256, 256>>>(emb, W1);
    kA2<<<21, 128>>>(cn, emb, W1, b1, W2, b2);
    kA3<<<129, 128>>>(b1, W2);
    kB<<<(129 * 129 + 127) / 128, 128, smB>>>(b1, W2);
    kC<<<8192, 256>>>(inst, out);
}

// round 6
// speedup vs baseline: 1.0166x; 1.0166x over previous
#include <cuda_runtime.h>

#define INVS2 0.70710678118654752440f

// ---------------- scratch (__device__ globals; no dynamic alloc) ----------------
__device__ __align__(128) float g_E1[129 * 128];        // emb @ W1
__device__ __align__(128) float g_wk[4 * 21 * 24];      // 0.5*Cl[c,k,:], k=1..4, pad 24
__device__ __align__(128) float g_w0[21 * 24];          // w[c,0], pad 24
__device__ __align__(128) float g_const[21];            // sum_t Cl[c,t,:]·b2
__device__ __align__(128) float g_C0[129 * 32];         // const[c] + p0(n0)·w[c,0]
__device__ __align__(128) float g_T[4 * 129 * 129 * 32];// T[k][n0][nk][c], pitch 32
__device__ int g_is64;

__device__ __forceinline__ int load_idx(const void* p, long long i, int is64) {
    return is64 ? (int)((const long long*)p)[i] : ((const int*)p)[i];
}

// ============== K1: fused detect + E1 + class-branch ============================
// block 0         : dtype detection on inst -> g_is64 (consumed by kC)
// blocks 1..65    : E1 = emb @ W1   (16512 elems, 256/block)
// blocks 66..86   : class branch (one class per block; self-detects cn dtype)
#define A1_BLOCKS 65
__global__ __launch_bounds__(256) void K1(const int* __restrict__ inst,
                                          const void* __restrict__ cn,
                                          const float* __restrict__ emb,
                                          const float* __restrict__ W1,
                                          const float* __restrict__ b1,
                                          const float* __restrict__ W2,
                                          const float* __restrict__ b2) {
    int b = blockIdx.x, t = threadIdx.x;
    if (b == 0) {
        // int64 values <129 have zero odd words; int32 node values are ~never
        // all-zero across 2048 odd words. Deterministic for a fixed input.
        __shared__ int any_nz;
        if (t == 0) any_nz = 0;
        __syncthreads();
        int nz = 0;
        for (int i = t; i < 2048; i += 256)
            if (inst[2 * i + 1] != 0) nz = 1;
        if (nz) atomicOr(&any_nz, 1);
        __syncthreads();
        if (t == 0) g_is64 = any_nz ? 0 : 1;
        return;
    }
    if (b <= A1_BLOCKS) {
        int o = (b - 1) * 256 + t;
        if (o < 129 * 128) {
            int i = o >> 7, j = o & 127;
            float acc = 0.f;
            #pragma unroll
            for (int d = 0; d < 21; d++) acc = fmaf(emb[i * 21 + d], W1[d * 128 + j], acc);
            g_E1[o] = acc;
        }
        return;
    }
    // ---- class branch, c = b - 66 ----
    int c = b - (A1_BLOCKS + 1);
    __shared__ float sx[105], sh[640], sr[640], sp[105], sCl[105];
    __shared__ int s_is64;
    if (t == 0) s_is64 = 1;
    __syncthreads();
    // self-detect cn dtype: odd int32 words of 105 int64 values
    if (t < 104) {
        if (((const int*)cn)[2 * t + 1] != 0) atomicAnd(&s_is64, 0);
    }
    __syncthreads();
    int is64 = s_is64;
    if (t < 105) {
        int s = t / 21, d = t - s * 21;
        int node = load_idx(cn, c * 5 + s, is64);
        sx[t] = emb[node * 21 + d];
    }
    __syncthreads();
    for (int o = t; o < 640; o += 256) {                 // xW1 [5,128]
        int s = o >> 7, j = o & 127;
        float a = 0.f;
        #pragma unroll
        for (int d = 0; d < 21; d++) a = fmaf(sx[s * 21 + d], W1[d * 128 + j], a);
        sh[o] = a;
    }
    __syncthreads();
    for (int o = t; o < 640; o += 256) {                 // prop + b1 + relu
        int s = o >> 7, j = o & 127;
        float v = (s == 0) ? sh[j] : fmaf(0.5f, sh[o], INVS2 * sh[j]);
        sr[o] = fmaxf(v + b1[j], 0.f);
    }
    __syncthreads();
    if (t < 105) {                                       // rW2 [5,21]
        int s = t / 21, d = t - s * 21;
        float a = 0.f;
        for (int j = 0; j < 128; j++) a = fmaf(sr[s * 128 + j], W2[j * 21 + d], a);
        sp[t] = a;
    }
    __syncthreads();
    if (t < 105) {                                       // Cl [5,21]
        int s = t / 21, d = t - s * 21;
        float v = (s == 0) ? sp[d] : fmaf(0.5f, sp[t], INVS2 * sp[d]);
        sCl[t] = v + b2[d];
    }
    __syncthreads();
    if (t < 96) {                                        // wk (pad 24)
        int k = t / 24, d = t - k * 24;
        g_wk[(k * 21 + c) * 24 + d] = (d < 21) ? 0.5f * sCl[(k + 1) * 21 + d] : 0.f;
    }
    if (t < 24)                                          // w0
        g_w0[c * 24 + t] = (t < 21)
            ? sCl[t] + INVS2 * (sCl[21 + t] + sCl[42 + t] + sCl[63 + t] + sCl[84 + t])
            : 0.f;
    if (t == 0) {
        float a = 0.f;
        for (int s = 0; s < 5; s++)
            for (int d = 0; d < 21; d++) a = fmaf(sCl[s * 21 + d], b2[d], a);
        g_const[c] = a;
    }
}

// ============== K2: build T tables AND C0 (C0 folded in as tail threads) ========
#define NPAIR 16641            // 129*129
#define NWORK 16770            // + 129 C0 rows
#define SE1_PAD 16644
__global__ __launch_bounds__(128) void K2(const float* __restrict__ b1,
                                          const float* __restrict__ W2) {
    extern __shared__ float sm[];
    float* sE1 = sm;                    // [129][129] pitch 129 (conflict-free)
    float* sW2 = sm + SE1_PAD;          // [128][24]
    float* sw  = sW2 + 128 * 24;        // [4][21][24]
    float* sw0 = sw + 4 * 21 * 24;      // [21][24]
    float* sC  = sw0 + 21 * 24;         // [32] const
    float* sb1 = sC + 32;               // [128]
    int t = threadIdx.x;
    for (int i = t; i < 129 * 128; i += 128)
        sE1[(i >> 7) * 129 + (i & 127)] = g_E1[i];
    for (int i = t; i < 128 * 24; i += 128) {
        int j = i / 24, d = i - j * 24;
        sW2[i] = (d < 21) ? W2[j * 21 + d] : 0.f;
    }
    for (int i = t; i < 4 * 21 * 24; i += 128) sw[i] = g_wk[i];
    for (int i = t; i < 21 * 24; i += 128) sw0[i] = g_w0[i];
    if (t < 32) sC[t] = (t < 21) ? g_const[t] : 0.f;
    sb1[t] = b1[t];
    __syncthreads();

    int flat = blockIdx.x * 128 + t;
    if (flat >= NWORK) return;
    bool isC0 = flat >= NPAIR;
    int n0, nk;
    float ca, cb;
    if (!isC0) { n0 = flat / 129; nk = flat - n0 * 129; ca = INVS2; cb = 0.5f; }
    else       { n0 = flat - NPAIR; nk = n0;            ca = 1.0f;  cb = 0.0f; }

    float p[21];
    #pragma unroll
    for (int d = 0; d < 21; d++) p[d] = 0.f;

    const float* e0 = &sE1[n0 * 129];
    const float* ek = &sE1[nk * 129];
    #pragma unroll 4
    for (int j = 0; j < 128; j++) {
        float rv = fmaxf(fmaf(cb, ek[j], fmaf(ca, e0[j], sb1[j])), 0.f);
        float q[24];
        const float4* w4 = (const float4*)&sW2[j * 24];
        *(float4*)&q[0]  = w4[0]; *(float4*)&q[4]  = w4[1];
        *(float4*)&q[8]  = w4[2]; *(float4*)&q[12] = w4[3];
        *(float4*)&q[16] = w4[4]; *(float4*)&q[20] = w4[5];
        #pragma unroll
        for (int d = 0; d < 21; d++) p[d] = fmaf(rv, q[d], p[d]);
    }

    if (!isC0) {
        #pragma unroll
        for (int k = 0; k < 4; k++) {
            float oc[24];
            #pragma unroll 3
            for (int c = 0; c < 21; c++) {
                float q[24];
                const float4* w4 = (const float4*)&sw[(k * 21 + c) * 24];
                *(float4*)&q[0]  = w4[0]; *(float4*)&q[4]  = w4[1];
                *(float4*)&q[8]  = w4[2]; *(float4*)&q[12] = w4[3];
                *(float4*)&q[16] = w4[4]; *(float4*)&q[20] = w4[5];
                float a0 = 0.f, a1 = 0.f, a2 = 0.f, a3 = 0.f;
                #pragma unroll
                for (int d = 0; d < 20; d += 4) {
                    a0 = fmaf(p[d + 0], q[d + 0], a0);
                    a1 = fmaf(p[d + 1], q[d + 1], a1);
                    a2 = fmaf(p[d + 2], q[d + 2], a2);
                    a3 = fmaf(p[d + 3], q[d + 3], a3);
                }
                a0 = fmaf(p[20], q[20], a0);
                oc[c] = (a0 + a1) + (a2 + a3);
            }
            oc[21] = 0.f; oc[22] = 0.f; oc[23] = 0.f;
            float4* d4 = (float4*)&g_T[(((k * 129) + n0) * 129 + nk) * 32];
            d4[0] = make_float4(oc[0],  oc[1],  oc[2],  oc[3]);
            d4[1] = make_float4(oc[4],  oc[5],  oc[6],  oc[7]);
            d4[2] = make_float4(oc[8],  oc[9],  oc[10], oc[11]);
            d4[3] = make_float4(oc[12], oc[13], oc[14], oc[15]);
            d4[4] = make_float4(oc[16], oc[17], oc[18], oc[19]);
            d4[5] = make_float4(oc[20], oc[21], oc[22], oc[23]);
        }
    } else {
        float oc[24];
        #pragma unroll 3
        for (int c = 0; c < 21; c++) {
            float v = sC[c];
            const float* q = &sw0[c * 24];
            #pragma unroll
            for (int d = 0; d < 21; d++) v = fmaf(p[d], q[d], v);
            oc[c] = v;
        }
        oc[21] = 0.f; oc[22] = 0.f; oc[23] = 0.f;
        float4* d4 = (float4*)&g_C0[n0 * 32];
        d4[0] = make_float4(oc[0],  oc[1],  oc[2],  oc[3]);
        d4[1] = make_float4(oc[4],  oc[5],  oc[6],  oc[7]);
        d4[2] = make_float4(oc[8],  oc[9],  oc[10], oc[11]);
        d4[3] = make_float4(oc[12], oc[13], oc[14], oc[15]);
        d4[4] = make_float4(oc[16], oc[17], oc[18], oc[19]);
        d4[5] = make_float4(oc[20], oc[21], oc[22], oc[23]);
    }
}

// ============== K3: per-pixel gather (8 threads/pixel, 6 active) ================
__global__ __launch_bounds__(256) void K3(const void* __restrict__ inst,
                                          float* __restrict__ out) {
    __shared__ float so[32 * 21];
    int t = threadIdx.x;
    int lane = t & 31, warp = t >> 5;
    int sub = lane >> 3, pp = lane & 7;
    int warpPix = blockIdx.x * 32 + warp * 4;
    long long base5 = (long long)warpPix * 5;
    int is64 = g_is64;
    int v = 0;
    if (lane < 20) v = load_idx(inst, base5 + lane, is64);
    int n0 = __shfl_sync(0xffffffffu, v, sub * 5);
    bool act = pp < 6;
    float4 acc = make_float4(0.f, 0.f, 0.f, 0.f);
    if (act) acc = *(const float4*)&g_C0[n0 * 32 + pp * 4];
    #pragma unroll
    for (int k = 0; k < 4; k++) {
        int nk = __shfl_sync(0xffffffffu, v, sub * 5 + k + 1);
        if (act) {
            float4 tv = *(const float4*)&g_T[(((k * 129) + n0) * 129 + nk) * 32 + pp * 4];
            acc.x += tv.x; acc.y += tv.y; acc.z += tv.z; acc.w += tv.w;
        }
    }
    int pib = warp * 4 + sub;
    if (act) {
        float vals[4] = {acc.x, acc.y, acc.z, acc.w};
        #pragma unroll
        for (int i = 0; i < 4; i++) {
            int c = pp * 4 + i;
            if (c < 21) so[pib * 21 + c] = vals[i];
        }
    }
    __syncthreads();
    const float4* s4 = (const float4*)so;
    float4* o4 = (float4*)(out + (long long)blockIdx.x * (32 * 21));
    if (t < 168) o4[t] = s4[t];
}

// ---------------- launch ---------------------------------------------------------
extern "C" void kernel_launch(void* const* d_in, const int* in_sizes, int n_in,
                              void* d_out, int out_size) {
    const void*  inst = d_in[0];                 // [4,256,256,5] int64/int32
    const void*  cn   = d_in[1];                 // [21,5]
    const float* emb  = (const float*)d_in[2];   // [129,21]
    const float* W1   = (const float*)d_in[3];   // [21,128]
    const float* b1   = (const float*)d_in[4];   // [128]
    const float* W2   = (const float*)d_in[5];   // [128,21]
    const float* b2   = (const float*)d_in[6];   // [21]
    float* out = (float*)d_out;

    const size_t smB = (size_t)(SE1_PAD + 128 * 24 + 4 * 21 * 24 + 21 * 24 + 32 + 128)
                       * sizeof(float);
    cudaFuncSetAttribute(K2, cudaFuncAttributeMaxDynamicSharedMemorySize, (int)smB);

    K1<<<1 + A1_BLOCKS + 21, 256>>>((const int*)inst, cn, emb, W1, b1, W2, b2);
    K2<<<(NWORK + 127) / 128, 128, smB>>>(b1, W2);
    K3<<<8192, 256>>>(inst, out);
}